// round 6
// baseline (speedup 1.0000x reference)
#include <cuda_runtime.h>
#include <math.h>

#define NMAXN 100000
#define NMAXE 1600000
#define INCH 61
#define OC 64
#define BN_EPS 1e-5f
#define SCAN_BLK 1024

// ------------- static device scratch (no allocation allowed) -------------
__device__ float4 d_A4[NMAXN * 16];   // per node: 64 ch; float4 g = channels 4g..4g+3
__device__ float4 d_Bp4[NMAXN * 16];  // pos @ W1[61:64]
__device__ int    d_deg[NMAXN];       // in-degree
__device__ int    d_odeg[NMAXN];      // out-degree
__device__ float  d_V[NMAXN * 3];     // V[n,r] = sum over out-edges of n of pos[dst,r]
__device__ int    d_scanned[NMAXN];
__device__ int    d_bsum[128];
__device__ int    d_rowptr[NMAXN + 1];
__device__ int    d_cursor[NMAXN];
__device__ int    d_csrc[NMAXE];      // src node per CSR slot (grouped by dst)
__device__ float  d_graw[NMAXE];      // gate pre-BN value per CSR slot
__device__ float  d_s1[OC];
__device__ float  d_s2[OC];
__device__ float  d_s3[OC];
__device__ float  d_s4[OC];
__device__ float  d_s5[OC];
__device__ float4 d_scale1[16];
__device__ float4 d_shift1[16];
__device__ float  d_gstats[2];
__device__ float  d_gparams[2];

// silu via single-MUFU tanh.approx:  silu(t) = u*(1+tanh(u)), u = t/2
__device__ __forceinline__ float silu_f(float t) {
    float u = 0.5f * t;
    float v;
    asm("tanh.approx.f32 %0, %1;" : "=f"(v) : "f"(u));
    return fmaf(u, v, u);
}

// ------------- K0: zero counters / stats -------------
__global__ void k_init(int n) {
    int i = blockIdx.x * blockDim.x + threadIdx.x;
    int st = gridDim.x * blockDim.x;
    for (int t = i; t < n; t += st) { d_deg[t] = 0; d_odeg[t] = 0; }
    for (int t = i; t < 3 * n; t += st) d_V[t] = 0.f;
    if (i < OC) { d_s1[i] = 0.f; d_s2[i] = 0.f; d_s3[i] = 0.f; d_s4[i] = 0.f; d_s5[i] = 0.f; }
    if (i < 2)  { d_gstats[i] = 0.f; }
}

// ------------- K1: per-node transform -------------
__global__ void k_node(const float* __restrict__ x, const float* __restrict__ pos,
                       const float* __restrict__ W1, int n) {
    __shared__ float2 sW[64 * 32];
    const float2* W2 = (const float2*)W1;
    for (int i = threadIdx.x; i < 64 * 32; i += blockDim.x) sW[i] = W2[i];
    __syncthreads();
    int lane = threadIdx.x & 31;
    int wid  = (blockIdx.x * blockDim.x + threadIdx.x) >> 5;
    int nw   = (gridDim.x * blockDim.x) >> 5;
    float2* A2  = (float2*)d_A4;
    float2* Bp2 = (float2*)d_Bp4;
    for (int nd = wid; nd < n; nd += nw) {
        float a0 = 0.f, a1 = 0.f, b0 = 0.f, b1v = 0.f;
        const float* xr = x + (long long)nd * INCH;
        #pragma unroll
        for (int k = 0; k < INCH; k++) {
            float xv = __ldg(xr + k);
            float2 w = sW[k * 32 + lane];
            a0 = fmaf(xv, w.x, a0);
            a1 = fmaf(xv, w.y, a1);
        }
        const float* pr = pos + (long long)nd * 3;
        #pragma unroll
        for (int k = 0; k < 3; k++) {
            float pv = __ldg(pr + k);
            float2 w = sW[(INCH + k) * 32 + lane];
            b0  = fmaf(pv, w.x, b0);
            b1v = fmaf(pv, w.y, b1v);
        }
        A2[nd * 32 + lane]  = make_float2(a0 + b0, a1 + b1v);
        Bp2[nd * 32 + lane] = make_float2(b0, b1v);
    }
}

// ------------- K2: degree histograms -------------
__global__ void k_count(const int* __restrict__ ei, int e, int n) {
    int i = blockIdx.x * blockDim.x + threadIdx.x;
    int st = gridDim.x * blockDim.x;
    for (; i < e; i += st) {
        unsigned s = (unsigned)ei[i];
        unsigned d = (unsigned)ei[e + i];
        if (d < (unsigned)n) atomicAdd(&d_deg[d], 1);
        if (s < (unsigned)n) atomicAdd(&d_odeg[s], 1);
    }
}

// ------------- K3a: per-block inclusive scan of deg -------------
__global__ void k_scanA(int n) {
    __shared__ int sh[32];
    int t = threadIdx.x, lane = t & 31, w = t >> 5;
    int idx = blockIdx.x * SCAN_BLK + t;
    int v = (idx < n) ? d_deg[idx] : 0;
    int xv = v;
    #pragma unroll
    for (int off = 1; off < 32; off <<= 1) {
        int y = __shfl_up_sync(0xffffffffu, xv, off);
        if (lane >= off) xv += y;
    }
    if (lane == 31) sh[w] = xv;
    __syncthreads();
    if (w == 0) {
        int y2 = sh[lane];
        #pragma unroll
        for (int off = 1; off < 32; off <<= 1) {
            int z = __shfl_up_sync(0xffffffffu, y2, off);
            if (lane >= off) y2 += z;
        }
        sh[lane] = y2;
    }
    __syncthreads();
    int incl = xv + ((w > 0) ? sh[w - 1] : 0);
    if (idx < n) d_scanned[idx] = incl;
    if (t == SCAN_BLK - 1) d_bsum[blockIdx.x] = incl;
}

// ------------- K3b: exclusive scan of block sums -------------
__global__ void k_scanB(int nb, int n) {
    __shared__ int sw[4];
    int t = threadIdx.x, lane = t & 31, w = t >> 5;
    int v = (t < nb) ? d_bsum[t] : 0;
    int xv = v;
    #pragma unroll
    for (int off = 1; off < 32; off <<= 1) {
        int y = __shfl_up_sync(0xffffffffu, xv, off);
        if (lane >= off) xv += y;
    }
    if (lane == 31) sw[w] = xv;
    __syncthreads();
    if (t == 0) {
        int run = 0;
        #pragma unroll
        for (int i = 0; i < 4; i++) { int tmp = sw[i]; sw[i] = run; run += tmp; }
    }
    __syncthreads();
    int incl = xv + sw[w];
    if (t < nb) d_bsum[t] = incl - v;
    if (t == nb - 1) d_rowptr[n] = incl;
}

// ------------- K3c: finalize rowptr/cursor -------------
__global__ void k_scanC(int n) {
    int idx = blockIdx.x * SCAN_BLK + threadIdx.x;
    if (idx < n) {
        int ex = d_scanned[idx] - d_deg[idx] + d_bsum[blockIdx.x];
        d_rowptr[idx] = ex;
        d_cursor[idx] = ex;
    }
}

// ------------- K4: scatter src ids into CSR slots + accumulate V[s] += pos[d] -------------
__global__ void k_scatter(const int* __restrict__ ei, const float* __restrict__ pos,
                          int e, int n) {
    int i = blockIdx.x * blockDim.x + threadIdx.x;
    int st = gridDim.x * blockDim.x;
    for (; i < e; i += st) {
        unsigned s = (unsigned)ei[i];
        unsigned d = (unsigned)ei[e + i];
        if (s >= (unsigned)n || d >= (unsigned)n) continue;
        int p = atomicAdd(&d_cursor[d], 1);
        d_csrc[p] = (int)s;
        const float* pd = pos + (size_t)d * 3;
        atomicAdd(&d_V[s * 3 + 0], pd[0]);
        atomicAdd(&d_V[s * 3 + 1], pd[1]);
        atomicAdd(&d_V[s * 3 + 2], pd[2]);
    }
}

// ------------- K5: node-level BN1 stats -------------
__global__ void k_zstats(const float* __restrict__ b1, const float* __restrict__ W1, int n) {
    int lane = threadIdx.x & 31;
    int wid  = (blockIdx.x * blockDim.x + threadIdx.x) >> 5;
    int nw   = (gridDim.x * blockDim.x) >> 5;
    const float2* A2  = (const float2*)d_A4;
    const float2* Bp2 = (const float2*)d_Bp4;
    float2 bias = ((const float2*)b1)[lane];
    float2 w61 = ((const float2*)(W1 + 61 * OC))[lane];
    float2 w62 = ((const float2*)(W1 + 62 * OC))[lane];
    float2 w63 = ((const float2*)(W1 + 63 * OC))[lane];
    float s1x = 0.f, s1y = 0.f, s2x = 0.f, s2y = 0.f, s3x = 0.f, s3y = 0.f;
    float s4x = 0.f, s4y = 0.f, s5x = 0.f, s5y = 0.f;
    for (int nd = wid; nd < n; nd += nw) {
        float od = (float)d_odeg[nd];
        float id = (float)d_deg[nd];
        float2 a  = A2[nd * 32 + lane];
        float2 bp = Bp2[nd * 32 + lane];
        float v0 = d_V[nd * 3 + 0], v1 = d_V[nd * 3 + 1], v2 = d_V[nd * 3 + 2];
        s1x = fmaf(od, a.x, s1x);          s1y = fmaf(od, a.y, s1y);
        s2x = fmaf(id, bp.x, s2x);         s2y = fmaf(id, bp.y, s2y);
        s3x = fmaf(od * a.x, a.x, s3x);    s3y = fmaf(od * a.y, a.y, s3y);
        float ox = bias.x - bp.x, oy = bias.y - bp.y;
        s4x = fmaf(id * ox, ox, s4x);      s4y = fmaf(id * oy, oy, s4y);
        float bvx = v0 * w61.x + v1 * w62.x + v2 * w63.x;
        float bvy = v0 * w61.y + v1 * w62.y + v2 * w63.y;
        s5x = fmaf(a.x, bvx, s5x);         s5y = fmaf(a.y, bvy, s5y);
    }
    atomicAdd(&d_s1[2 * lane], s1x);     atomicAdd(&d_s1[2 * lane + 1], s1y);
    atomicAdd(&d_s2[2 * lane], s2x);     atomicAdd(&d_s2[2 * lane + 1], s2y);
    atomicAdd(&d_s3[2 * lane], s3x);     atomicAdd(&d_s3[2 * lane + 1], s3y);
    atomicAdd(&d_s4[2 * lane], s4x);     atomicAdd(&d_s4[2 * lane + 1], s4y);
    atomicAdd(&d_s5[2 * lane], s5x);     atomicAdd(&d_s5[2 * lane + 1], s5y);
}

// ------------- K6: finalize BN1 params -------------
__global__ void k_bn1(const float* __restrict__ g1, const float* __restrict__ be1,
                      const float* __restrict__ b1, float Ef) {
    int c = threadIdx.x;
    float bc = b1[c];
    float sumz  = d_s1[c] + Ef * bc - d_s2[c];
    float sumz2 = d_s3[c] + d_s4[c] + 2.0f * (bc * d_s1[c] - d_s5[c]);
    float mu  = sumz / Ef;
    float var = sumz2 / Ef - mu * mu;
    float sc  = g1[c] * rsqrtf(var + BN_EPS);
    ((float*)d_scale1)[c] = sc;
    ((float*)d_shift1)[c] = be1[c] - mu * sc;
}

// ------------- K7: gate_raw per edge + gate stats (half-warp per edge, float4) -------------
__global__ void k_gate(const float* __restrict__ b1, const float* __restrict__ Wg,
                       const float* __restrict__ bg, int n) {
    int lane = threadIdx.x & 31;
    int half = lane >> 4;        // 0 or 1
    int hl   = lane & 15;        // channel quad index
    int wid  = (blockIdx.x * blockDim.x + threadIdx.x) >> 5;
    int nw   = (gridDim.x * blockDim.x) >> 5;
    float4 bias = ((const float4*)b1)[hl];
    float4 sc = d_scale1[hl];
    float4 sh = d_shift1[hl];
    float4 wg = ((const float4*)Wg)[hl];
    float bgv = bg[0];
    float sg = 0.f, sg2 = 0.f;
    for (int nd = wid; nd < n; nd += nw) {
        int r0 = d_rowptr[nd], r1 = d_rowptr[nd + 1];
        if (r0 == r1) continue;
        float4 bp = d_Bp4[nd * 16 + hl];
        float ox = bias.x - bp.x, oy = bias.y - bp.y;
        float oz = bias.z - bp.z, ow = bias.w - bp.w;
        int j = r0;
        // main: 4 edges per iteration, 2 per half-warp
        for (; j + 4 <= r1; j += 4) {
            int sa = d_csrc[j + half];
            int sb = d_csrc[j + 2 + half];
            float4 aa = d_A4[sa * 16 + hl];
            float4 ab = d_A4[sb * 16 + hl];
            float qa = silu_f(fmaf(aa.x + ox, sc.x, sh.x)) * wg.x
                     + silu_f(fmaf(aa.y + oy, sc.y, sh.y)) * wg.y
                     + silu_f(fmaf(aa.z + oz, sc.z, sh.z)) * wg.z
                     + silu_f(fmaf(aa.w + ow, sc.w, sh.w)) * wg.w;
            float qb = silu_f(fmaf(ab.x + ox, sc.x, sh.x)) * wg.x
                     + silu_f(fmaf(ab.y + oy, sc.y, sh.y)) * wg.y
                     + silu_f(fmaf(ab.z + oz, sc.z, sh.z)) * wg.z
                     + silu_f(fmaf(ab.w + ow, sc.w, sh.w)) * wg.w;
            #pragma unroll
            for (int off = 8; off; off >>= 1) {
                qa += __shfl_xor_sync(0xffffffffu, qa, off);
                qb += __shfl_xor_sync(0xffffffffu, qb, off);
            }
            if (hl == 0) {
                float pa = qa + bgv, pb = qb + bgv;
                d_graw[j + half] = pa;
                d_graw[j + 2 + half] = pb;
                sg += pa + pb;
                sg2 = fmaf(pa, pa, sg2);
                sg2 = fmaf(pb, pb, sg2);
            }
        }
        // mid: 2 edges, 1 per half-warp
        if (j + 2 <= r1) {
            int sa = d_csrc[j + half];
            float4 aa = d_A4[sa * 16 + hl];
            float qa = silu_f(fmaf(aa.x + ox, sc.x, sh.x)) * wg.x
                     + silu_f(fmaf(aa.y + oy, sc.y, sh.y)) * wg.y
                     + silu_f(fmaf(aa.z + oz, sc.z, sh.z)) * wg.z
                     + silu_f(fmaf(aa.w + ow, sc.w, sh.w)) * wg.w;
            #pragma unroll
            for (int off = 8; off; off >>= 1)
                qa += __shfl_xor_sync(0xffffffffu, qa, off);
            if (hl == 0) {
                float pa = qa + bgv;
                d_graw[j + half] = pa;
                sg += pa;
                sg2 = fmaf(pa, pa, sg2);
            }
            j += 2;
        }
        // tail: single edge, both halves cover all 64 channels
        if (j < r1) {
            int s0 = d_csrc[j];
            float4 a0 = d_A4[s0 * 16 + hl];
            float q = silu_f(fmaf(a0.x + ox, sc.x, sh.x)) * wg.x
                    + silu_f(fmaf(a0.y + oy, sc.y, sh.y)) * wg.y
                    + silu_f(fmaf(a0.z + oz, sc.z, sh.z)) * wg.z
                    + silu_f(fmaf(a0.w + ow, sc.w, sh.w)) * wg.w;
            #pragma unroll
            for (int off = 8; off; off >>= 1)
                q += __shfl_xor_sync(0xffffffffu, q, off);
            if (lane == 0) {
                float p = q + bgv;
                d_graw[j] = p;
                sg += p;
                sg2 = fmaf(p, p, sg2);
            }
        }
    }
    // combine the two half-leaders (lanes 0 and 16)
    sg  += __shfl_xor_sync(0xffffffffu, sg, 16);
    sg2 += __shfl_xor_sync(0xffffffffu, sg2, 16);
    if (lane == 0) {
        atomicAdd(&d_gstats[0], sg);
        atomicAdd(&d_gstats[1], sg2);
    }
}

// ------------- K8: finalize gate BN params -------------
__global__ void k_bng(const float* __restrict__ gg, const float* __restrict__ bgb, float Ef) {
    float mu  = d_gstats[0] / Ef;
    float var = d_gstats[1] / Ef - mu * mu;
    float sc  = gg[0] * rsqrtf(var + BN_EPS);
    d_gparams[0] = sc;
    d_gparams[1] = bgb[0] - mu * sc;
}

// ------------- K9: fused softmax + weighted aggregate (single sweep; normalize at end) ----
// out = (sum_j e_j * h_j) / (sum_j e_j + 1e-16), e_j = exp(silu(BN(graw_j)))
__global__ void k_agg(const float* __restrict__ b1, float* __restrict__ out, int n) {
    int lane = threadIdx.x & 31;
    int half = lane >> 4;
    int hl   = lane & 15;
    int wid  = (blockIdx.x * blockDim.x + threadIdx.x) >> 5;
    int nw   = (gridDim.x * blockDim.x) >> 5;
    float4 bias = ((const float4*)b1)[hl];
    float4 sc = d_scale1[hl];
    float4 sh = d_shift1[hl];
    float gsc = d_gparams[0], gsh = d_gparams[1];
    float4* out4 = (float4*)out;
    for (int nd = wid; nd < n; nd += nw) {
        int r0 = d_rowptr[nd], r1 = d_rowptr[nd + 1];
        if (r0 == r1) {
            if (half == 0) out4[nd * 16 + hl] = make_float4(0.f, 0.f, 0.f, 0.f);
            continue;
        }
        float4 bp = d_Bp4[nd * 16 + hl];
        float ox = bias.x - bp.x, oy = bias.y - bp.y;
        float oz = bias.z - bp.z, ow = bias.w - bp.w;
        float ax = 0.f, ay = 0.f, az = 0.f, aw = 0.f;
        float ssum = 0.f;
        int j = r0;
        // main: 4 edges per iteration; lanes 0-3 compute the 4 exp weights
        for (; j + 4 <= r1; j += 4) {
            float ee = 0.f;
            if (lane < 4) {
                float g = silu_f(fmaf(d_graw[j + lane], gsc, gsh));
                ee = __expf(g);
                ssum += ee;
            }
            float wa = __shfl_sync(0xffffffffu, ee, half);
            float wb = __shfl_sync(0xffffffffu, ee, 2 + half);
            int sa = d_csrc[j + half];
            int sb = d_csrc[j + 2 + half];
            float4 aa = d_A4[sa * 16 + hl];
            float4 ab = d_A4[sb * 16 + hl];
            ax = fmaf(wa, silu_f(fmaf(aa.x + ox, sc.x, sh.x)), ax);
            ay = fmaf(wa, silu_f(fmaf(aa.y + oy, sc.y, sh.y)), ay);
            az = fmaf(wa, silu_f(fmaf(aa.z + oz, sc.z, sh.z)), az);
            aw = fmaf(wa, silu_f(fmaf(aa.w + ow, sc.w, sh.w)), aw);
            ax = fmaf(wb, silu_f(fmaf(ab.x + ox, sc.x, sh.x)), ax);
            ay = fmaf(wb, silu_f(fmaf(ab.y + oy, sc.y, sh.y)), ay);
            az = fmaf(wb, silu_f(fmaf(ab.z + oz, sc.z, sh.z)), az);
            aw = fmaf(wb, silu_f(fmaf(ab.w + ow, sc.w, sh.w)), aw);
        }
        // mid: 2 edges; lanes 0-1 compute weights
        if (j + 2 <= r1) {
            float ee = 0.f;
            if (lane < 2) {
                float g = silu_f(fmaf(d_graw[j + lane], gsc, gsh));
                ee = __expf(g);
                ssum += ee;
            }
            float wa = __shfl_sync(0xffffffffu, ee, half);
            int sa = d_csrc[j + half];
            float4 aa = d_A4[sa * 16 + hl];
            ax = fmaf(wa, silu_f(fmaf(aa.x + ox, sc.x, sh.x)), ax);
            ay = fmaf(wa, silu_f(fmaf(aa.y + oy, sc.y, sh.y)), ay);
            az = fmaf(wa, silu_f(fmaf(aa.z + oz, sc.z, sh.z)), az);
            aw = fmaf(wa, silu_f(fmaf(aa.w + ow, sc.w, sh.w)), aw);
            j += 2;
        }
        // tail: single edge, both halves load same channels; weight only half 0
        if (j < r1) {
            float g = silu_f(fmaf(d_graw[j], gsc, gsh));
            float e = __expf(g);
            if (lane == 0) ssum += e;
            float w0 = (half == 0) ? e : 0.0f;
            int s0 = d_csrc[j];
            float4 a0 = d_A4[s0 * 16 + hl];
            ax = fmaf(w0, silu_f(fmaf(a0.x + ox, sc.x, sh.x)), ax);
            ay = fmaf(w0, silu_f(fmaf(a0.y + oy, sc.y, sh.y)), ay);
            az = fmaf(w0, silu_f(fmaf(a0.z + oz, sc.z, sh.z)), az);
            aw = fmaf(w0, silu_f(fmaf(a0.w + ow, sc.w, sh.w)), aw);
        }
        // total weight sum (lanes 0-3 hold partials; butterfly sums once)
        #pragma unroll
        for (int off = 16; off; off >>= 1)
            ssum += __shfl_xor_sync(0xffffffffu, ssum, off);
        float inv = 1.0f / (ssum + 1e-16f);
        // merge the two halves' edge subsets and normalize
        ax += __shfl_xor_sync(0xffffffffu, ax, 16);
        ay += __shfl_xor_sync(0xffffffffu, ay, 16);
        az += __shfl_xor_sync(0xffffffffu, az, 16);
        aw += __shfl_xor_sync(0xffffffffu, aw, 16);
        if (half == 0)
            out4[nd * 16 + hl] = make_float4(ax * inv, ay * inv, az * inv, aw * inv);
    }
}

// ------------- launch -------------
extern "C" void kernel_launch(void* const* d_in, const int* in_sizes, int n_in,
                              void* d_out, int out_size) {
    const float* x   = (const float*)d_in[0];
    const float* pos = (const float*)d_in[1];
    const int*   ei  = (const int*)d_in[2];   // int32 [2, E]
    const float* W1  = (const float*)d_in[3];
    const float* b1  = (const float*)d_in[4];
    const float* g1  = (const float*)d_in[5];
    const float* be1 = (const float*)d_in[6];
    const float* Wg  = (const float*)d_in[7];
    const float* bg  = (const float*)d_in[8];
    const float* gg  = (const float*)d_in[9];
    const float* bgb = (const float*)d_in[10];
    float* out = (float*)d_out;

    int n = in_sizes[0] / INCH;   // 100000
    int e = in_sizes[2] / 2;      // 1600000
    int nb = (n + SCAN_BLK - 1) / SCAN_BLK;

    k_init   <<<256, 256>>>(n);
    k_node   <<<512, 256>>>(x, pos, W1, n);
    k_count  <<<512, 256>>>(ei, e, n);
    k_scanA  <<<nb, SCAN_BLK>>>(n);
    k_scanB  <<<1, 128>>>(nb, n);
    k_scanC  <<<nb, SCAN_BLK>>>(n);
    k_scatter<<<512, 256>>>(ei, pos, e, n);
    k_zstats <<<256, 256>>>(b1, W1, n);
    k_bn1    <<<1, 64>>>(g1, be1, b1, (float)e);
    k_gate   <<<1024, 256>>>(b1, Wg, bg, n);
    k_bng    <<<1, 1>>>(gg, bgb, (float)e);
    k_agg    <<<1024, 256>>>(b1, out, n);
}

// round 7
// speedup vs baseline: 1.0434x; 1.0434x over previous
#include <cuda_runtime.h>
#include <cuda_fp16.h>
#include <math.h>

#define NMAXN 100000
#define NMAXE 1600000
#define INCH 61
#define OC 64
#define BN_EPS 1e-5f
#define SCAN_BLK 1024

// ------------- static device scratch (no allocation allowed) -------------
__device__ uint4  d_Ah[NMAXN * 8];    // 64 ch fp16 per node (128 B): A = x@W1[:61]+pos@W1[61:]
__device__ float4 d_Bp4[NMAXN * 16];  // pos @ W1[61:64], fp32
__device__ int    d_deg[NMAXN];       // in-degree
__device__ int    d_odeg[NMAXN];      // out-degree
__device__ float  d_V[NMAXN * 3];     // V[n,r] = sum over out-edges of n of pos[dst,r]
__device__ int    d_scanned[NMAXN];
__device__ int    d_bsum[128];
__device__ int    d_rowptr[NMAXN + 1];
__device__ int    d_cursor[NMAXN];
__device__ int    d_csrc[NMAXE];      // src node per CSR slot (grouped by dst)
__device__ float  d_graw[NMAXE];      // gate value per CSR slot (staged: raw -> e)
__device__ float  d_s1[OC];
__device__ float  d_s2[OC];
__device__ float  d_s3[OC];
__device__ float  d_s4[OC];
__device__ float  d_s5[OC];
__device__ float4 d_scale1[16];
__device__ float4 d_shift1[16];
__device__ float  d_gstats[2];
__device__ float  d_gparams[2];

// silu via single-MUFU tanh.approx:  silu(t) = u*(1+tanh(u)), u = t/2
__device__ __forceinline__ float silu_f(float t) {
    float u = 0.5f * t;
    float v;
    asm("tanh.approx.f32 %0, %1;" : "=f"(v) : "f"(u));
    return fmaf(u, v, u);
}

// ------------- K0: zero counters / stats -------------
__global__ void k_init(int n) {
    int i = blockIdx.x * blockDim.x + threadIdx.x;
    int st = gridDim.x * blockDim.x;
    for (int t = i; t < n; t += st) { d_deg[t] = 0; d_odeg[t] = 0; }
    for (int t = i; t < 3 * n; t += st) d_V[t] = 0.f;
    if (i < OC) { d_s1[i] = 0.f; d_s2[i] = 0.f; d_s3[i] = 0.f; d_s4[i] = 0.f; d_s5[i] = 0.f; }
    if (i < 2)  { d_gstats[i] = 0.f; }
}

// ------------- K1: per-node transform (A stored fp16, Bp fp32) -------------
__global__ void k_node(const float* __restrict__ x, const float* __restrict__ pos,
                       const float* __restrict__ W1, int n) {
    __shared__ float2 sW[64 * 32];
    const float2* W2 = (const float2*)W1;
    for (int i = threadIdx.x; i < 64 * 32; i += blockDim.x) sW[i] = W2[i];
    __syncthreads();
    int lane = threadIdx.x & 31;
    int wid  = (blockIdx.x * blockDim.x + threadIdx.x) >> 5;
    int nw   = (gridDim.x * blockDim.x) >> 5;
    __half2* Ah2 = (__half2*)d_Ah;
    float2*  Bp2 = (float2*)d_Bp4;
    for (int nd = wid; nd < n; nd += nw) {
        float a0 = 0.f, a1 = 0.f, b0 = 0.f, b1v = 0.f;
        const float* xr = x + (long long)nd * INCH;
        #pragma unroll
        for (int k = 0; k < INCH; k++) {
            float xv = __ldg(xr + k);
            float2 w = sW[k * 32 + lane];
            a0 = fmaf(xv, w.x, a0);
            a1 = fmaf(xv, w.y, a1);
        }
        const float* pr = pos + (long long)nd * 3;
        #pragma unroll
        for (int k = 0; k < 3; k++) {
            float pv = __ldg(pr + k);
            float2 w = sW[(INCH + k) * 32 + lane];
            b0  = fmaf(pv, w.x, b0);
            b1v = fmaf(pv, w.y, b1v);
        }
        Ah2[nd * 32 + lane] = __floats2half2_rn(a0 + b0, a1 + b1v);
        Bp2[nd * 32 + lane] = make_float2(b0, b1v);
    }
}

// ------------- K2: degree histograms -------------
__global__ void k_count(const int* __restrict__ ei, int e, int n) {
    int i = blockIdx.x * blockDim.x + threadIdx.x;
    int st = gridDim.x * blockDim.x;
    for (; i < e; i += st) {
        unsigned s = (unsigned)ei[i];
        unsigned d = (unsigned)ei[e + i];
        if (d < (unsigned)n) atomicAdd(&d_deg[d], 1);
        if (s < (unsigned)n) atomicAdd(&d_odeg[s], 1);
    }
}

// ------------- K3a: per-block inclusive scan of deg -------------
__global__ void k_scanA(int n) {
    __shared__ int sh[32];
    int t = threadIdx.x, lane = t & 31, w = t >> 5;
    int idx = blockIdx.x * SCAN_BLK + t;
    int v = (idx < n) ? d_deg[idx] : 0;
    int xv = v;
    #pragma unroll
    for (int off = 1; off < 32; off <<= 1) {
        int y = __shfl_up_sync(0xffffffffu, xv, off);
        if (lane >= off) xv += y;
    }
    if (lane == 31) sh[w] = xv;
    __syncthreads();
    if (w == 0) {
        int y2 = sh[lane];
        #pragma unroll
        for (int off = 1; off < 32; off <<= 1) {
            int z = __shfl_up_sync(0xffffffffu, y2, off);
            if (lane >= off) y2 += z;
        }
        sh[lane] = y2;
    }
    __syncthreads();
    int incl = xv + ((w > 0) ? sh[w - 1] : 0);
    if (idx < n) d_scanned[idx] = incl;
    if (t == SCAN_BLK - 1) d_bsum[blockIdx.x] = incl;
}

// ------------- K3b: exclusive scan of block sums -------------
__global__ void k_scanB(int nb, int n) {
    __shared__ int sw[4];
    int t = threadIdx.x, lane = t & 31, w = t >> 5;
    int v = (t < nb) ? d_bsum[t] : 0;
    int xv = v;
    #pragma unroll
    for (int off = 1; off < 32; off <<= 1) {
        int y = __shfl_up_sync(0xffffffffu, xv, off);
        if (lane >= off) xv += y;
    }
    if (lane == 31) sw[w] = xv;
    __syncthreads();
    if (t == 0) {
        int run = 0;
        #pragma unroll
        for (int i = 0; i < 4; i++) { int tmp = sw[i]; sw[i] = run; run += tmp; }
    }
    __syncthreads();
    int incl = xv + sw[w];
    if (t < nb) d_bsum[t] = incl - v;
    if (t == nb - 1) d_rowptr[n] = incl;
}

// ------------- K3c: finalize rowptr/cursor -------------
__global__ void k_scanC(int n) {
    int idx = blockIdx.x * SCAN_BLK + threadIdx.x;
    if (idx < n) {
        int ex = d_scanned[idx] - d_deg[idx] + d_bsum[blockIdx.x];
        d_rowptr[idx] = ex;
        d_cursor[idx] = ex;
    }
}

// ------------- K4: scatter src ids into CSR slots + accumulate V[s] += pos[d] -------------
__global__ void k_scatter(const int* __restrict__ ei, const float* __restrict__ pos,
                          int e, int n) {
    int i = blockIdx.x * blockDim.x + threadIdx.x;
    int st = gridDim.x * blockDim.x;
    for (; i < e; i += st) {
        unsigned s = (unsigned)ei[i];
        unsigned d = (unsigned)ei[e + i];
        if (s >= (unsigned)n || d >= (unsigned)n) continue;
        int p = atomicAdd(&d_cursor[d], 1);
        d_csrc[p] = (int)s;
        const float* pd = pos + (size_t)d * 3;
        atomicAdd(&d_V[s * 3 + 0], pd[0]);
        atomicAdd(&d_V[s * 3 + 1], pd[1]);
        atomicAdd(&d_V[s * 3 + 2], pd[2]);
    }
}

// ------------- K5: node-level BN1 stats (uses the fp16 A for self-consistency) -------------
__global__ void k_zstats(const float* __restrict__ b1, const float* __restrict__ W1, int n) {
    int lane = threadIdx.x & 31;
    int wid  = (blockIdx.x * blockDim.x + threadIdx.x) >> 5;
    int nw   = (gridDim.x * blockDim.x) >> 5;
    const __half2* Ah2 = (const __half2*)d_Ah;
    const float2*  Bp2 = (const float2*)d_Bp4;
    float2 bias = ((const float2*)b1)[lane];
    float2 w61 = ((const float2*)(W1 + 61 * OC))[lane];
    float2 w62 = ((const float2*)(W1 + 62 * OC))[lane];
    float2 w63 = ((const float2*)(W1 + 63 * OC))[lane];
    float s1x = 0.f, s1y = 0.f, s2x = 0.f, s2y = 0.f, s3x = 0.f, s3y = 0.f;
    float s4x = 0.f, s4y = 0.f, s5x = 0.f, s5y = 0.f;
    for (int nd = wid; nd < n; nd += nw) {
        float od = (float)d_odeg[nd];
        float id = (float)d_deg[nd];
        float2 a  = __half22float2(Ah2[nd * 32 + lane]);
        float2 bp = Bp2[nd * 32 + lane];
        float v0 = d_V[nd * 3 + 0], v1 = d_V[nd * 3 + 1], v2 = d_V[nd * 3 + 2];
        s1x = fmaf(od, a.x, s1x);          s1y = fmaf(od, a.y, s1y);
        s2x = fmaf(id, bp.x, s2x);         s2y = fmaf(id, bp.y, s2y);
        s3x = fmaf(od * a.x, a.x, s3x);    s3y = fmaf(od * a.y, a.y, s3y);
        float ox = bias.x - bp.x, oy = bias.y - bp.y;
        s4x = fmaf(id * ox, ox, s4x);      s4y = fmaf(id * oy, oy, s4y);
        float bvx = v0 * w61.x + v1 * w62.x + v2 * w63.x;
        float bvy = v0 * w61.y + v1 * w62.y + v2 * w63.y;
        s5x = fmaf(a.x, bvx, s5x);         s5y = fmaf(a.y, bvy, s5y);
    }
    atomicAdd(&d_s1[2 * lane], s1x);     atomicAdd(&d_s1[2 * lane + 1], s1y);
    atomicAdd(&d_s2[2 * lane], s2x);     atomicAdd(&d_s2[2 * lane + 1], s2y);
    atomicAdd(&d_s3[2 * lane], s3x);     atomicAdd(&d_s3[2 * lane + 1], s3y);
    atomicAdd(&d_s4[2 * lane], s4x);     atomicAdd(&d_s4[2 * lane + 1], s4y);
    atomicAdd(&d_s5[2 * lane], s5x);     atomicAdd(&d_s5[2 * lane + 1], s5y);
}

// ------------- K6: finalize BN1 params -------------
__global__ void k_bn1(const float* __restrict__ g1, const float* __restrict__ be1,
                      const float* __restrict__ b1, float Ef) {
    int c = threadIdx.x;
    float bc = b1[c];
    float sumz  = d_s1[c] + Ef * bc - d_s2[c];
    float sumz2 = d_s3[c] + d_s4[c] + 2.0f * (bc * d_s1[c] - d_s5[c]);
    float mu  = sumz / Ef;
    float var = sumz2 / Ef - mu * mu;
    float sc  = g1[c] * rsqrtf(var + BN_EPS);
    ((float*)d_scale1)[c] = sc;
    ((float*)d_shift1)[c] = be1[c] - mu * sc;
}

// ------------- K7: gate_raw per edge + gate stats (quarter-warp per edge, fp16 gather) ----
__global__ void k_gate(const float* __restrict__ b1, const float* __restrict__ Wg,
                       const float* __restrict__ bg, int n) {
    int lane = threadIdx.x & 31;
    int q  = lane >> 3;       // quarter (edge slot 0..3)
    int ql = lane & 7;        // channel octet: channels 8ql..8ql+7
    int wid  = (blockIdx.x * blockDim.x + threadIdx.x) >> 5;
    int nw   = (gridDim.x * blockDim.x) >> 5;
    float4 biasA = ((const float4*)b1)[ql * 2],     biasB = ((const float4*)b1)[ql * 2 + 1];
    float4 scA = d_scale1[ql * 2],  scB = d_scale1[ql * 2 + 1];
    float4 shA = d_shift1[ql * 2],  shB = d_shift1[ql * 2 + 1];
    float4 wgA = ((const float4*)Wg)[ql * 2],       wgB = ((const float4*)Wg)[ql * 2 + 1];
    float bgv = bg[0];
    float sg = 0.f, sg2 = 0.f;
    for (int nd = wid; nd < n; nd += nw) {
        int r0 = d_rowptr[nd], r1 = d_rowptr[nd + 1];
        if (r0 == r1) continue;
        float4 bpA = d_Bp4[nd * 16 + ql * 2];
        float4 bpB = d_Bp4[nd * 16 + ql * 2 + 1];
        float oAx = biasA.x - bpA.x, oAy = biasA.y - bpA.y;
        float oAz = biasA.z - bpA.z, oAw = biasA.w - bpA.w;
        float oBx = biasB.x - bpB.x, oBy = biasB.y - bpB.y;
        float oBz = biasB.z - bpB.z, oBw = biasB.w - bpB.w;
        int j = r0;
        // main: 4 edges per iteration, one per quarter
        for (; j + 4 <= r1; j += 4) {
            int s = d_csrc[j + q];
            uint4 raw = d_Ah[s * 8 + ql];
            const __half2* hp = (const __half2*)&raw;
            float2 a01 = __half22float2(hp[0]);
            float2 a23 = __half22float2(hp[1]);
            float2 a45 = __half22float2(hp[2]);
            float2 a67 = __half22float2(hp[3]);
            float p = silu_f(fmaf(a01.x + oAx, scA.x, shA.x)) * wgA.x
                    + silu_f(fmaf(a01.y + oAy, scA.y, shA.y)) * wgA.y
                    + silu_f(fmaf(a23.x + oAz, scA.z, shA.z)) * wgA.z
                    + silu_f(fmaf(a23.y + oAw, scA.w, shA.w)) * wgA.w
                    + silu_f(fmaf(a45.x + oBx, scB.x, shB.x)) * wgB.x
                    + silu_f(fmaf(a45.y + oBy, scB.y, shB.y)) * wgB.y
                    + silu_f(fmaf(a67.x + oBz, scB.z, shB.z)) * wgB.z
                    + silu_f(fmaf(a67.y + oBw, scB.w, shB.w)) * wgB.w;
            #pragma unroll
            for (int off = 4; off; off >>= 1)
                p += __shfl_xor_sync(0xffffffffu, p, off);
            if (ql == 0) {
                p += bgv;
                d_graw[j + q] = p;
                sg += p;
                sg2 = fmaf(p, p, sg2);
            }
        }
        // tail: rem in {1,2,3}; quarters q<rem active, single iteration
        int rem = r1 - j;
        if (rem > 0) {
            bool act = (q < rem);
            int jj = j + (act ? q : 0);
            int s = d_csrc[jj];
            uint4 raw = d_Ah[s * 8 + ql];
            const __half2* hp = (const __half2*)&raw;
            float2 a01 = __half22float2(hp[0]);
            float2 a23 = __half22float2(hp[1]);
            float2 a45 = __half22float2(hp[2]);
            float2 a67 = __half22float2(hp[3]);
            float p = silu_f(fmaf(a01.x + oAx, scA.x, shA.x)) * wgA.x
                    + silu_f(fmaf(a01.y + oAy, scA.y, shA.y)) * wgA.y
                    + silu_f(fmaf(a23.x + oAz, scA.z, shA.z)) * wgA.z
                    + silu_f(fmaf(a23.y + oAw, scA.w, shA.w)) * wgA.w
                    + silu_f(fmaf(a45.x + oBx, scB.x, shB.x)) * wgB.x
                    + silu_f(fmaf(a45.y + oBy, scB.y, shB.y)) * wgB.y
                    + silu_f(fmaf(a67.x + oBz, scB.z, shB.z)) * wgB.z
                    + silu_f(fmaf(a67.y + oBw, scB.w, shB.w)) * wgB.w;
            #pragma unroll
            for (int off = 4; off; off >>= 1)
                p += __shfl_xor_sync(0xffffffffu, p, off);
            if (ql == 0 && act) {
                p += bgv;
                d_graw[jj] = p;
                sg += p;
                sg2 = fmaf(p, p, sg2);
            }
        }
    }
    // combine the four quarter-leaders (lanes 0, 8, 16, 24)
    sg  += __shfl_xor_sync(0xffffffffu, sg, 8);
    sg2 += __shfl_xor_sync(0xffffffffu, sg2, 8);
    sg  += __shfl_xor_sync(0xffffffffu, sg, 16);
    sg2 += __shfl_xor_sync(0xffffffffu, sg2, 16);
    if (lane == 0) {
        atomicAdd(&d_gstats[0], sg);
        atomicAdd(&d_gstats[1], sg2);
    }
}

// ------------- K8: finalize gate BN params -------------
__global__ void k_bng(const float* __restrict__ gg, const float* __restrict__ bgb, float Ef) {
    float mu  = d_gstats[0] / Ef;
    float var = d_gstats[1] / Ef - mu * mu;
    float sc  = gg[0] * rsqrtf(var + BN_EPS);
    d_gparams[0] = sc;
    d_gparams[1] = bgb[0] - mu * sc;
}

// ------------- K9: softmax (no max-shift; silu output bounded) + weighted aggregate ------
__global__ void k_agg(const float* __restrict__ b1, float* __restrict__ out, int n) {
    int lane = threadIdx.x & 31;
    int q  = lane >> 3;
    int ql = lane & 7;
    int wid  = (blockIdx.x * blockDim.x + threadIdx.x) >> 5;
    int nw   = (gridDim.x * blockDim.x) >> 5;
    float4 biasA = ((const float4*)b1)[ql * 2],     biasB = ((const float4*)b1)[ql * 2 + 1];
    float4 scA = d_scale1[ql * 2],  scB = d_scale1[ql * 2 + 1];
    float4 shA = d_shift1[ql * 2],  shB = d_shift1[ql * 2 + 1];
    float gsc = d_gparams[0], gsh = d_gparams[1];
    float4* out4 = (float4*)out;
    for (int nd = wid; nd < n; nd += nw) {
        int r0 = d_rowptr[nd], r1 = d_rowptr[nd + 1];
        if (r0 == r1) {
            if (q == 0) {
                out4[nd * 16 + ql * 2]     = make_float4(0.f, 0.f, 0.f, 0.f);
                out4[nd * 16 + ql * 2 + 1] = make_float4(0.f, 0.f, 0.f, 0.f);
            }
            continue;
        }
        // pass A: e = exp(silu(BN(p))); store e; sum (warp-strided)
        float ssum = 0.f;
        for (int j = r0 + lane; j < r1; j += 32) {
            float g = silu_f(fmaf(d_graw[j], gsc, gsh));
            float e = __expf(g);
            d_graw[j] = e;
            ssum += e;
        }
        #pragma unroll
        for (int off = 16; off; off >>= 1)
            ssum += __shfl_xor_sync(0xffffffffu, ssum, off);
        float inv = 1.0f / (ssum + 1e-16f);
        __syncwarp();
        // pass B: weighted aggregate, 4 edges per iteration (one per quarter)
        float4 bpA = d_Bp4[nd * 16 + ql * 2];
        float4 bpB = d_Bp4[nd * 16 + ql * 2 + 1];
        float oAx = biasA.x - bpA.x, oAy = biasA.y - bpA.y;
        float oAz = biasA.z - bpA.z, oAw = biasA.w - bpA.w;
        float oBx = biasB.x - bpB.x, oBy = biasB.y - bpB.y;
        float oBz = biasB.z - bpB.z, oBw = biasB.w - bpB.w;
        float4 accA = make_float4(0.f, 0.f, 0.f, 0.f);
        float4 accB = make_float4(0.f, 0.f, 0.f, 0.f);
        int j = r0;
        for (; j + 4 <= r1; j += 4) {
            int s = d_csrc[j + q];
            float w = d_graw[j + q] * inv;
            uint4 raw = d_Ah[s * 8 + ql];
            const __half2* hp = (const __half2*)&raw;
            float2 a01 = __half22float2(hp[0]);
            float2 a23 = __half22float2(hp[1]);
            float2 a45 = __half22float2(hp[2]);
            float2 a67 = __half22float2(hp[3]);
            accA.x = fmaf(w, silu_f(fmaf(a01.x + oAx, scA.x, shA.x)), accA.x);
            accA.y = fmaf(w, silu_f(fmaf(a01.y + oAy, scA.y, shA.y)), accA.y);
            accA.z = fmaf(w, silu_f(fmaf(a23.x + oAz, scA.z, shA.z)), accA.z);
            accA.w = fmaf(w, silu_f(fmaf(a23.y + oAw, scA.w, shA.w)), accA.w);
            accB.x = fmaf(w, silu_f(fmaf(a45.x + oBx, scB.x, shB.x)), accB.x);
            accB.y = fmaf(w, silu_f(fmaf(a45.y + oBy, scB.y, shB.y)), accB.y);
            accB.z = fmaf(w, silu_f(fmaf(a67.x + oBz, scB.z, shB.z)), accB.z);
            accB.w = fmaf(w, silu_f(fmaf(a67.y + oBw, scB.w, shB.w)), accB.w);
        }
        int rem = r1 - j;
        if (rem > 0) {
            bool act = (q < rem);
            int jj = j + (act ? q : 0);
            int s = d_csrc[jj];
            float w = act ? d_graw[jj] * inv : 0.0f;
            uint4 raw = d_Ah[s * 8 + ql];
            const __half2* hp = (const __half2*)&raw;
            float2 a01 = __half22float2(hp[0]);
            float2 a23 = __half22float2(hp[1]);
            float2 a45 = __half22float2(hp[2]);
            float2 a67 = __half22float2(hp[3]);
            accA.x = fmaf(w, silu_f(fmaf(a01.x + oAx, scA.x, shA.x)), accA.x);
            accA.y = fmaf(w, silu_f(fmaf(a01.y + oAy, scA.y, shA.y)), accA.y);
            accA.z = fmaf(w, silu_f(fmaf(a23.x + oAz, scA.z, shA.z)), accA.z);
            accA.w = fmaf(w, silu_f(fmaf(a23.y + oAw, scA.w, shA.w)), accA.w);
            accB.x = fmaf(w, silu_f(fmaf(a45.x + oBx, scB.x, shB.x)), accB.x);
            accB.y = fmaf(w, silu_f(fmaf(a45.y + oBy, scB.y, shB.y)), accB.y);
            accB.z = fmaf(w, silu_f(fmaf(a67.x + oBz, scB.z, shB.z)), accB.z);
            accB.w = fmaf(w, silu_f(fmaf(a67.y + oBw, scB.w, shB.w)), accB.w);
        }
        // merge quarters: xor 8, xor 16 -> lanes 0..7 hold channel totals
        #pragma unroll
        for (int off = 8; off <= 16; off <<= 1) {
            accA.x += __shfl_xor_sync(0xffffffffu, accA.x, off);
            accA.y += __shfl_xor_sync(0xffffffffu, accA.y, off);
            accA.z += __shfl_xor_sync(0xffffffffu, accA.z, off);
            accA.w += __shfl_xor_sync(0xffffffffu, accA.w, off);
            accB.x += __shfl_xor_sync(0xffffffffu, accB.x, off);
            accB.y += __shfl_xor_sync(0xffffffffu, accB.y, off);
            accB.z += __shfl_xor_sync(0xffffffffu, accB.z, off);
            accB.w += __shfl_xor_sync(0xffffffffu, accB.w, off);
        }
        if (q == 0) {
            out4[nd * 16 + ql * 2]     = accA;
            out4[nd * 16 + ql * 2 + 1] = accB;
        }
    }
}

// ------------- launch -------------
extern "C" void kernel_launch(void* const* d_in, const int* in_sizes, int n_in,
                              void* d_out, int out_size) {
    const float* x   = (const float*)d_in[0];
    const float* pos = (const float*)d_in[1];
    const int*   ei  = (const int*)d_in[2];   // int32 [2, E]
    const float* W1  = (const float*)d_in[3];
    const float* b1  = (const float*)d_in[4];
    const float* g1  = (const float*)d_in[5];
    const float* be1 = (const float*)d_in[6];
    const float* Wg  = (const float*)d_in[7];
    const float* bg  = (const float*)d_in[8];
    const float* gg  = (const float*)d_in[9];
    const float* bgb = (const float*)d_in[10];
    float* out = (float*)d_out;

    int n = in_sizes[0] / INCH;   // 100000
    int e = in_sizes[2] / 2;      // 1600000
    int nb = (n + SCAN_BLK - 1) / SCAN_BLK;

    k_init   <<<256, 256>>>(n);
    k_node   <<<512, 256>>>(x, pos, W1, n);
    k_count  <<<512, 256>>>(ei, e, n);
    k_scanA  <<<nb, SCAN_BLK>>>(n);
    k_scanB  <<<1, 128>>>(nb, n);
    k_scanC  <<<nb, SCAN_BLK>>>(n);
    k_scatter<<<512, 256>>>(ei, pos, e, n);
    k_zstats <<<256, 256>>>(b1, W1, n);
    k_bn1    <<<1, 64>>>(g1, be1, b1, (float)e);
    k_gate   <<<1024, 256>>>(b1, Wg, bg, n);
    k_bng    <<<1, 1>>>(gg, bgb, (float)e);
    k_agg    <<<1024, 256>>>(b1, out, n);
}

// round 8
// speedup vs baseline: 1.0751x; 1.0304x over previous
#include <cuda_runtime.h>
#include <cuda_fp16.h>
#include <math.h>

#define NMAXN 100000
#define NMAXE 1600000
#define INCH 61
#define OC 64
#define BN_EPS 1e-5f
#define SCAN_BLK 1024

// ------------- static device scratch (no allocation allowed) -------------
__device__ uint4  d_Ah[NMAXN * 8];    // 64 ch fp16 per node (128 B)
__device__ float4 d_Bp4[NMAXN * 16];  // pos @ W1[61:64], fp32
__device__ int    d_deg[NMAXN];
__device__ int    d_odeg[NMAXN];
__device__ float  d_V[NMAXN * 3];
__device__ int    d_scanned[NMAXN];
__device__ int    d_bsum[128];
__device__ int    d_rowptr[NMAXN + 1];
__device__ int    d_cursor[NMAXN];
__device__ int    d_csrc[NMAXE];
__device__ float  d_graw[NMAXE];
__device__ float  d_s1[OC];
__device__ float  d_s2[OC];
__device__ float  d_s3[OC];
__device__ float  d_s4[OC];
__device__ float  d_s5[OC];
__device__ float4 d_scale1[16];
__device__ float4 d_shift1[16];
__device__ float  d_gstats[2];
__device__ float  d_gparams[2];

__device__ __forceinline__ float silu_f(float t) {
    float u = 0.5f * t;
    float v;
    asm("tanh.approx.f32 %0, %1;" : "=f"(v) : "f"(u));
    return fmaf(u, v, u);
}

struct Oct {  // per-octet channel constants (8 channels)
    float4 oA, oB, scA, scB, shA, shB;
};

// silu(BN(A+o)) dot wg over 8 channels held in one uint4 of half2
__device__ __forceinline__ float dot8(const uint4& raw, const Oct& c,
                                      const float4& wgA, const float4& wgB) {
    const __half2* hp = (const __half2*)&raw;
    float2 a01 = __half22float2(hp[0]);
    float2 a23 = __half22float2(hp[1]);
    float2 a45 = __half22float2(hp[2]);
    float2 a67 = __half22float2(hp[3]);
    return silu_f(fmaf(a01.x + c.oA.x, c.scA.x, c.shA.x)) * wgA.x
         + silu_f(fmaf(a01.y + c.oA.y, c.scA.y, c.shA.y)) * wgA.y
         + silu_f(fmaf(a23.x + c.oA.z, c.scA.z, c.shA.z)) * wgA.z
         + silu_f(fmaf(a23.y + c.oA.w, c.scA.w, c.shA.w)) * wgA.w
         + silu_f(fmaf(a45.x + c.oB.x, c.scB.x, c.shB.x)) * wgB.x
         + silu_f(fmaf(a45.y + c.oB.y, c.scB.y, c.shB.y)) * wgB.y
         + silu_f(fmaf(a67.x + c.oB.z, c.scB.z, c.shB.z)) * wgB.z
         + silu_f(fmaf(a67.y + c.oB.w, c.scB.w, c.shB.w)) * wgB.w;
}

// accA/accB += w * silu(BN(A+o)) over 8 channels
__device__ __forceinline__ void acc8(const uint4& raw, const Oct& c, float w,
                                     float4& accA, float4& accB) {
    const __half2* hp = (const __half2*)&raw;
    float2 a01 = __half22float2(hp[0]);
    float2 a23 = __half22float2(hp[1]);
    float2 a45 = __half22float2(hp[2]);
    float2 a67 = __half22float2(hp[3]);
    accA.x = fmaf(w, silu_f(fmaf(a01.x + c.oA.x, c.scA.x, c.shA.x)), accA.x);
    accA.y = fmaf(w, silu_f(fmaf(a01.y + c.oA.y, c.scA.y, c.shA.y)), accA.y);
    accA.z = fmaf(w, silu_f(fmaf(a23.x + c.oA.z, c.scA.z, c.shA.z)), accA.z);
    accA.w = fmaf(w, silu_f(fmaf(a23.y + c.oA.w, c.scA.w, c.shA.w)), accA.w);
    accB.x = fmaf(w, silu_f(fmaf(a45.x + c.oB.x, c.scB.x, c.shB.x)), accB.x);
    accB.y = fmaf(w, silu_f(fmaf(a45.y + c.oB.y, c.scB.y, c.shB.y)), accB.y);
    accB.z = fmaf(w, silu_f(fmaf(a67.x + c.oB.z, c.scB.z, c.shB.z)), accB.z);
    accB.w = fmaf(w, silu_f(fmaf(a67.y + c.oB.w, c.scB.w, c.shB.w)), accB.w);
}

// ------------- K0 -------------
__global__ void k_init(int n) {
    int i = blockIdx.x * blockDim.x + threadIdx.x;
    int st = gridDim.x * blockDim.x;
    for (int t = i; t < n; t += st) { d_deg[t] = 0; d_odeg[t] = 0; }
    for (int t = i; t < 3 * n; t += st) d_V[t] = 0.f;
    if (i < OC) { d_s1[i] = 0.f; d_s2[i] = 0.f; d_s3[i] = 0.f; d_s4[i] = 0.f; d_s5[i] = 0.f; }
    if (i < 2)  { d_gstats[i] = 0.f; }
}

// ------------- K1: per-node transform -------------
__global__ void k_node(const float* __restrict__ x, const float* __restrict__ pos,
                       const float* __restrict__ W1, int n) {
    __shared__ float2 sW[64 * 32];
    const float2* W2 = (const float2*)W1;
    for (int i = threadIdx.x; i < 64 * 32; i += blockDim.x) sW[i] = W2[i];
    __syncthreads();
    int lane = threadIdx.x & 31;
    int wid  = (blockIdx.x * blockDim.x + threadIdx.x) >> 5;
    int nw   = (gridDim.x * blockDim.x) >> 5;
    __half2* Ah2 = (__half2*)d_Ah;
    float2*  Bp2 = (float2*)d_Bp4;
    for (int nd = wid; nd < n; nd += nw) {
        float a0 = 0.f, a1 = 0.f, b0 = 0.f, b1v = 0.f;
        const float* xr = x + (long long)nd * INCH;
        #pragma unroll
        for (int k = 0; k < INCH; k++) {
            float xv = __ldg(xr + k);
            float2 w = sW[k * 32 + lane];
            a0 = fmaf(xv, w.x, a0);
            a1 = fmaf(xv, w.y, a1);
        }
        const float* pr = pos + (long long)nd * 3;
        #pragma unroll
        for (int k = 0; k < 3; k++) {
            float pv = __ldg(pr + k);
            float2 w = sW[(INCH + k) * 32 + lane];
            b0  = fmaf(pv, w.x, b0);
            b1v = fmaf(pv, w.y, b1v);
        }
        Ah2[nd * 32 + lane] = __floats2half2_rn(a0 + b0, a1 + b1v);
        Bp2[nd * 32 + lane] = make_float2(b0, b1v);
    }
}

// ------------- K2 -------------
__global__ void k_count(const int* __restrict__ ei, int e, int n) {
    int i = blockIdx.x * blockDim.x + threadIdx.x;
    int st = gridDim.x * blockDim.x;
    for (; i < e; i += st) {
        unsigned s = (unsigned)ei[i];
        unsigned d = (unsigned)ei[e + i];
        if (d < (unsigned)n) atomicAdd(&d_deg[d], 1);
        if (s < (unsigned)n) atomicAdd(&d_odeg[s], 1);
    }
}

// ------------- K3a -------------
__global__ void k_scanA(int n) {
    __shared__ int sh[32];
    int t = threadIdx.x, lane = t & 31, w = t >> 5;
    int idx = blockIdx.x * SCAN_BLK + t;
    int v = (idx < n) ? d_deg[idx] : 0;
    int xv = v;
    #pragma unroll
    for (int off = 1; off < 32; off <<= 1) {
        int y = __shfl_up_sync(0xffffffffu, xv, off);
        if (lane >= off) xv += y;
    }
    if (lane == 31) sh[w] = xv;
    __syncthreads();
    if (w == 0) {
        int y2 = sh[lane];
        #pragma unroll
        for (int off = 1; off < 32; off <<= 1) {
            int z = __shfl_up_sync(0xffffffffu, y2, off);
            if (lane >= off) y2 += z;
        }
        sh[lane] = y2;
    }
    __syncthreads();
    int incl = xv + ((w > 0) ? sh[w - 1] : 0);
    if (idx < n) d_scanned[idx] = incl;
    if (t == SCAN_BLK - 1) d_bsum[blockIdx.x] = incl;
}

// ------------- K3b -------------
__global__ void k_scanB(int nb, int n) {
    __shared__ int sw[4];
    int t = threadIdx.x, lane = t & 31, w = t >> 5;
    int v = (t < nb) ? d_bsum[t] : 0;
    int xv = v;
    #pragma unroll
    for (int off = 1; off < 32; off <<= 1) {
        int y = __shfl_up_sync(0xffffffffu, xv, off);
        if (lane >= off) xv += y;
    }
    if (lane == 31) sw[w] = xv;
    __syncthreads();
    if (t == 0) {
        int run = 0;
        #pragma unroll
        for (int i = 0; i < 4; i++) { int tmp = sw[i]; sw[i] = run; run += tmp; }
    }
    __syncthreads();
    int incl = xv + sw[w];
    if (t < nb) d_bsum[t] = incl - v;
    if (t == nb - 1) d_rowptr[n] = incl;
}

// ------------- K3c -------------
__global__ void k_scanC(int n) {
    int idx = blockIdx.x * SCAN_BLK + threadIdx.x;
    if (idx < n) {
        int ex = d_scanned[idx] - d_deg[idx] + d_bsum[blockIdx.x];
        d_rowptr[idx] = ex;
        d_cursor[idx] = ex;
    }
}

// ------------- K4 -------------
__global__ void k_scatter(const int* __restrict__ ei, const float* __restrict__ pos,
                          int e, int n) {
    int i = blockIdx.x * blockDim.x + threadIdx.x;
    int st = gridDim.x * blockDim.x;
    for (; i < e; i += st) {
        unsigned s = (unsigned)ei[i];
        unsigned d = (unsigned)ei[e + i];
        if (s >= (unsigned)n || d >= (unsigned)n) continue;
        int p = atomicAdd(&d_cursor[d], 1);
        d_csrc[p] = (int)s;
        const float* pd = pos + (size_t)d * 3;
        atomicAdd(&d_V[s * 3 + 0], pd[0]);
        atomicAdd(&d_V[s * 3 + 1], pd[1]);
        atomicAdd(&d_V[s * 3 + 2], pd[2]);
    }
}

// ------------- K5: node-level BN1 stats -------------
__global__ void k_zstats(const float* __restrict__ b1, const float* __restrict__ W1, int n) {
    int lane = threadIdx.x & 31;
    int wid  = (blockIdx.x * blockDim.x + threadIdx.x) >> 5;
    int nw   = (gridDim.x * blockDim.x) >> 5;
    const __half2* Ah2 = (const __half2*)d_Ah;
    const float2*  Bp2 = (const float2*)d_Bp4;
    float2 bias = ((const float2*)b1)[lane];
    float2 w61 = ((const float2*)(W1 + 61 * OC))[lane];
    float2 w62 = ((const float2*)(W1 + 62 * OC))[lane];
    float2 w63 = ((const float2*)(W1 + 63 * OC))[lane];
    float s1x = 0.f, s1y = 0.f, s2x = 0.f, s2y = 0.f, s3x = 0.f, s3y = 0.f;
    float s4x = 0.f, s4y = 0.f, s5x = 0.f, s5y = 0.f;
    for (int nd = wid; nd < n; nd += nw) {
        float od = (float)d_odeg[nd];
        float id = (float)d_deg[nd];
        float2 a  = __half22float2(Ah2[nd * 32 + lane]);
        float2 bp = Bp2[nd * 32 + lane];
        float v0 = d_V[nd * 3 + 0], v1 = d_V[nd * 3 + 1], v2 = d_V[nd * 3 + 2];
        s1x = fmaf(od, a.x, s1x);          s1y = fmaf(od, a.y, s1y);
        s2x = fmaf(id, bp.x, s2x);         s2y = fmaf(id, bp.y, s2y);
        s3x = fmaf(od * a.x, a.x, s3x);    s3y = fmaf(od * a.y, a.y, s3y);
        float ox = bias.x - bp.x, oy = bias.y - bp.y;
        s4x = fmaf(id * ox, ox, s4x);      s4y = fmaf(id * oy, oy, s4y);
        float bvx = v0 * w61.x + v1 * w62.x + v2 * w63.x;
        float bvy = v0 * w61.y + v1 * w62.y + v2 * w63.y;
        s5x = fmaf(a.x, bvx, s5x);         s5y = fmaf(a.y, bvy, s5y);
    }
    atomicAdd(&d_s1[2 * lane], s1x);     atomicAdd(&d_s1[2 * lane + 1], s1y);
    atomicAdd(&d_s2[2 * lane], s2x);     atomicAdd(&d_s2[2 * lane + 1], s2y);
    atomicAdd(&d_s3[2 * lane], s3x);     atomicAdd(&d_s3[2 * lane + 1], s3y);
    atomicAdd(&d_s4[2 * lane], s4x);     atomicAdd(&d_s4[2 * lane + 1], s4y);
    atomicAdd(&d_s5[2 * lane], s5x);     atomicAdd(&d_s5[2 * lane + 1], s5y);
}

// ------------- K6 -------------
__global__ void k_bn1(const float* __restrict__ g1, const float* __restrict__ be1,
                      const float* __restrict__ b1, float Ef) {
    int c = threadIdx.x;
    float bc = b1[c];
    float sumz  = d_s1[c] + Ef * bc - d_s2[c];
    float sumz2 = d_s3[c] + d_s4[c] + 2.0f * (bc * d_s1[c] - d_s5[c]);
    float mu  = sumz / Ef;
    float var = sumz2 / Ef - mu * mu;
    float sc  = g1[c] * rsqrtf(var + BN_EPS);
    ((float*)d_scale1)[c] = sc;
    ((float*)d_shift1)[c] = be1[c] - mu * sc;
}

// ------------- K7: gate (quarter-warp per edge, 8 edges/iter for MLP) -------------
__global__ void k_gate(const float* __restrict__ b1, const float* __restrict__ Wg,
                       const float* __restrict__ bg, int n) {
    int lane = threadIdx.x & 31;
    int q  = lane >> 3;
    int ql = lane & 7;
    int wid  = (blockIdx.x * blockDim.x + threadIdx.x) >> 5;
    int nw   = (gridDim.x * blockDim.x) >> 5;
    float4 biasA = ((const float4*)b1)[ql * 2], biasB = ((const float4*)b1)[ql * 2 + 1];
    Oct c;
    c.scA = d_scale1[ql * 2];  c.scB = d_scale1[ql * 2 + 1];
    c.shA = d_shift1[ql * 2];  c.shB = d_shift1[ql * 2 + 1];
    float4 wgA = ((const float4*)Wg)[ql * 2], wgB = ((const float4*)Wg)[ql * 2 + 1];
    float bgv = bg[0];
    float sg = 0.f, sg2 = 0.f;
    for (int nd = wid; nd < n; nd += nw) {
        int r0 = d_rowptr[nd], r1 = d_rowptr[nd + 1];
        if (r0 == r1) continue;
        float4 bpA = d_Bp4[nd * 16 + ql * 2];
        float4 bpB = d_Bp4[nd * 16 + ql * 2 + 1];
        c.oA = make_float4(biasA.x - bpA.x, biasA.y - bpA.y, biasA.z - bpA.z, biasA.w - bpA.w);
        c.oB = make_float4(biasB.x - bpB.x, biasB.y - bpB.y, biasB.z - bpB.z, biasB.w - bpB.w);
        int j = r0;
        // 8 edges per iteration: 2 per quarter, loads batched for MLP
        for (; j + 8 <= r1; j += 8) {
            int s0 = d_csrc[j + q];
            int s1 = d_csrc[j + 4 + q];
            uint4 raw0 = d_Ah[s0 * 8 + ql];
            uint4 raw1 = d_Ah[s1 * 8 + ql];
            float p0 = dot8(raw0, c, wgA, wgB);
            float p1 = dot8(raw1, c, wgA, wgB);
            #pragma unroll
            for (int off = 4; off; off >>= 1) {
                p0 += __shfl_xor_sync(0xffffffffu, p0, off);
                p1 += __shfl_xor_sync(0xffffffffu, p1, off);
            }
            if (ql == 0) {
                p0 += bgv; p1 += bgv;
                d_graw[j + q] = p0;
                d_graw[j + 4 + q] = p1;
                sg += p0 + p1;
                sg2 = fmaf(p0, p0, sg2);
                sg2 = fmaf(p1, p1, sg2);
            }
        }
        // 4 edges
        if (j + 4 <= r1) {
            int s = d_csrc[j + q];
            uint4 raw = d_Ah[s * 8 + ql];
            float p = dot8(raw, c, wgA, wgB);
            #pragma unroll
            for (int off = 4; off; off >>= 1)
                p += __shfl_xor_sync(0xffffffffu, p, off);
            if (ql == 0) {
                p += bgv;
                d_graw[j + q] = p;
                sg += p;
                sg2 = fmaf(p, p, sg2);
            }
            j += 4;
        }
        // remainder 1..3 (predicated quarters)
        int rem = r1 - j;
        if (rem > 0) {
            bool act = (q < rem);
            int jj = j + (act ? q : 0);
            int s = d_csrc[jj];
            uint4 raw = d_Ah[s * 8 + ql];
            float p = dot8(raw, c, wgA, wgB);
            #pragma unroll
            for (int off = 4; off; off >>= 1)
                p += __shfl_xor_sync(0xffffffffu, p, off);
            if (ql == 0 && act) {
                p += bgv;
                d_graw[jj] = p;
                sg += p;
                sg2 = fmaf(p, p, sg2);
            }
        }
    }
    sg  += __shfl_xor_sync(0xffffffffu, sg, 8);
    sg2 += __shfl_xor_sync(0xffffffffu, sg2, 8);
    sg  += __shfl_xor_sync(0xffffffffu, sg, 16);
    sg2 += __shfl_xor_sync(0xffffffffu, sg2, 16);
    if (lane == 0) {
        atomicAdd(&d_gstats[0], sg);
        atomicAdd(&d_gstats[1], sg2);
    }
}

// ------------- K8 -------------
__global__ void k_bng(const float* __restrict__ gg, const float* __restrict__ bgb, float Ef) {
    float mu  = d_gstats[0] / Ef;
    float var = d_gstats[1] / Ef - mu * mu;
    float sc  = gg[0] * rsqrtf(var + BN_EPS);
    d_gparams[0] = sc;
    d_gparams[1] = bgb[0] - mu * sc;
}

// ------------- K9: softmax + weighted aggregate (8 edges/iter in pass B) -------------
__global__ void k_agg(const float* __restrict__ b1, float* __restrict__ out, int n) {
    int lane = threadIdx.x & 31;
    int q  = lane >> 3;
    int ql = lane & 7;
    int wid  = (blockIdx.x * blockDim.x + threadIdx.x) >> 5;
    int nw   = (gridDim.x * blockDim.x) >> 5;
    float4 biasA = ((const float4*)b1)[ql * 2], biasB = ((const float4*)b1)[ql * 2 + 1];
    Oct c;
    c.scA = d_scale1[ql * 2];  c.scB = d_scale1[ql * 2 + 1];
    c.shA = d_shift1[ql * 2];  c.shB = d_shift1[ql * 2 + 1];
    float gsc = d_gparams[0], gsh = d_gparams[1];
    float4* out4 = (float4*)out;
    for (int nd = wid; nd < n; nd += nw) {
        int r0 = d_rowptr[nd], r1 = d_rowptr[nd + 1];
        if (r0 == r1) {
            if (q == 0) {
                out4[nd * 16 + ql * 2]     = make_float4(0.f, 0.f, 0.f, 0.f);
                out4[nd * 16 + ql * 2 + 1] = make_float4(0.f, 0.f, 0.f, 0.f);
            }
            continue;
        }
        // pass A: e = exp(silu(BN(p))); store e; sum
        float ssum = 0.f;
        for (int j = r0 + lane; j < r1; j += 32) {
            float g = silu_f(fmaf(d_graw[j], gsc, gsh));
            float e = __expf(g);
            d_graw[j] = e;
            ssum += e;
        }
        #pragma unroll
        for (int off = 16; off; off >>= 1)
            ssum += __shfl_xor_sync(0xffffffffu, ssum, off);
        float inv = 1.0f / (ssum + 1e-16f);
        __syncwarp();
        // pass B: weighted aggregate, 8 edges/iter
        float4 bpA = d_Bp4[nd * 16 + ql * 2];
        float4 bpB = d_Bp4[nd * 16 + ql * 2 + 1];
        c.oA = make_float4(biasA.x - bpA.x, biasA.y - bpA.y, biasA.z - bpA.z, biasA.w - bpA.w);
        c.oB = make_float4(biasB.x - bpB.x, biasB.y - bpB.y, biasB.z - bpB.z, biasB.w - bpB.w);
        float4 accA = make_float4(0.f, 0.f, 0.f, 0.f);
        float4 accB = make_float4(0.f, 0.f, 0.f, 0.f);
        int j = r0;
        for (; j + 8 <= r1; j += 8) {
            int s0 = d_csrc[j + q];
            int s1 = d_csrc[j + 4 + q];
            float w0 = d_graw[j + q] * inv;
            float w1 = d_graw[j + 4 + q] * inv;
            uint4 raw0 = d_Ah[s0 * 8 + ql];
            uint4 raw1 = d_Ah[s1 * 8 + ql];
            acc8(raw0, c, w0, accA, accB);
            acc8(raw1, c, w1, accA, accB);
        }
        if (j + 4 <= r1) {
            int s = d_csrc[j + q];
            float w = d_graw[j + q] * inv;
            uint4 raw = d_Ah[s * 8 + ql];
            acc8(raw, c, w, accA, accB);
            j += 4;
        }
        int rem = r1 - j;
        if (rem > 0) {
            bool act = (q < rem);
            int jj = j + (act ? q : 0);
            int s = d_csrc[jj];
            float w = act ? d_graw[jj] * inv : 0.0f;
            uint4 raw = d_Ah[s * 8 + ql];
            acc8(raw, c, w, accA, accB);
        }
        #pragma unroll
        for (int off = 8; off <= 16; off <<= 1) {
            accA.x += __shfl_xor_sync(0xffffffffu, accA.x, off);
            accA.y += __shfl_xor_sync(0xffffffffu, accA.y, off);
            accA.z += __shfl_xor_sync(0xffffffffu, accA.z, off);
            accA.w += __shfl_xor_sync(0xffffffffu, accA.w, off);
            accB.x += __shfl_xor_sync(0xffffffffu, accB.x, off);
            accB.y += __shfl_xor_sync(0xffffffffu, accB.y, off);
            accB.z += __shfl_xor_sync(0xffffffffu, accB.z, off);
            accB.w += __shfl_xor_sync(0xffffffffu, accB.w, off);
        }
        if (q == 0) {
            out4[nd * 16 + ql * 2]     = accA;
            out4[nd * 16 + ql * 2 + 1] = accB;
        }
    }
}

// ------------- launch -------------
extern "C" void kernel_launch(void* const* d_in, const int* in_sizes, int n_in,
                              void* d_out, int out_size) {
    const float* x   = (const float*)d_in[0];
    const float* pos = (const float*)d_in[1];
    const int*   ei  = (const int*)d_in[2];
    const float* W1  = (const float*)d_in[3];
    const float* b1  = (const float*)d_in[4];
    const float* g1  = (const float*)d_in[5];
    const float* be1 = (const float*)d_in[6];
    const float* Wg  = (const float*)d_in[7];
    const float* bg  = (const float*)d_in[8];
    const float* gg  = (const float*)d_in[9];
    const float* bgb = (const float*)d_in[10];
    float* out = (float*)d_out;

    int n = in_sizes[0] / INCH;   // 100000
    int e = in_sizes[2] / 2;      // 1600000
    int nb = (n + SCAN_BLK - 1) / SCAN_BLK;

    k_init   <<<256, 256>>>(n);
    k_node   <<<512, 256>>>(x, pos, W1, n);
    k_count  <<<512, 256>>>(ei, e, n);
    k_scanA  <<<nb, SCAN_BLK>>>(n);
    k_scanB  <<<1, 128>>>(nb, n);
    k_scanC  <<<nb, SCAN_BLK>>>(n);
    k_scatter<<<512, 256>>>(ei, pos, e, n);
    k_zstats <<<256, 256>>>(b1, W1, n);
    k_bn1    <<<1, 64>>>(g1, be1, b1, (float)e);
    k_gate   <<<1024, 256>>>(b1, Wg, bg, n);
    k_bng    <<<1, 1>>>(gg, bgb, (float)e);
    k_agg    <<<1024, 256>>>(b1, out, n);
}